// round 1
// baseline (speedup 1.0000x reference)
#include <cuda_runtime.h>
#include <math.h>

// Model dims
#define Ln 16
#define Hn 8
#define Dn 768
#define Fn 2048
#define Vn 32000
#define DHn 96
#define Bn 2
#define Sn 1024
#define NTOK (Bn*Sn)        // 2048 tokens

typedef long long ll;

// ---------------- scratch (device globals; no allocations allowed) ----------
__device__ float g_x [NTOK*Dn];          // residual stream
__device__ float g_xn[NTOK*Dn];          // normed activations
__device__ float g_q [NTOK*Dn];
__device__ float g_k [NTOK*Dn];
__device__ float g_v [NTOK*Dn];
__device__ float g_o [NTOK*Dn];
__device__ float g_sc[Bn*Hn*Sn*Sn];      // attention scores/probs (64M floats? no: 16.7M)
__device__ float g_ff[NTOK*Fn];          // FFN hidden

// ---------------- helpers ---------------------------------------------------
__device__ __forceinline__ float gelu_tanh(float x) {
    float x3 = x * x * x;
    return 0.5f * x * (1.0f + tanhf(0.7978845608028654f * (x + 0.044715f * x3)));
}

__device__ __forceinline__ float block_reduce_sum(float v) {
    __shared__ float red[8];
    int lane = threadIdx.x & 31, wid = threadIdx.x >> 5;
    #pragma unroll
    for (int o = 16; o > 0; o >>= 1) v += __shfl_down_sync(0xffffffffu, v, o);
    __syncthreads();                       // protect red[] reuse across calls
    if (lane == 0) red[wid] = v;
    __syncthreads();
    float r = (threadIdx.x < 8) ? red[threadIdx.x] : 0.0f;
    if (wid == 0) {
        #pragma unroll
        for (int o = 4; o > 0; o >>= 1) r += __shfl_down_sync(0xffu, r, o);
        if (lane == 0) red[0] = r;
    }
    __syncthreads();
    return red[0];
}

__device__ __forceinline__ float block_reduce_max(float v) {
    __shared__ float redm[8];
    int lane = threadIdx.x & 31, wid = threadIdx.x >> 5;
    #pragma unroll
    for (int o = 16; o > 0; o >>= 1) v = fmaxf(v, __shfl_down_sync(0xffffffffu, v, o));
    __syncthreads();
    if (lane == 0) redm[wid] = v;
    __syncthreads();
    float r = (threadIdx.x < 8) ? redm[threadIdx.x] : -3.0e38f;
    if (wid == 0) {
        #pragma unroll
        for (int o = 4; o > 0; o >>= 1) r = fmaxf(r, __shfl_down_sync(0xffu, r, o));
        if (lane == 0) redm[0] = r;
    }
    __syncthreads();
    return redm[0];
}

// ---------------- fused embed + rmsnorm ------------------------------------
// x[r,:] = rmsnorm(tok_emb[tok[r]] + pos_emb[r % S], pos_norm_w)
__global__ __launch_bounds__(256)
void embed_norm_kernel(const int* __restrict__ tok,
                       const float* __restrict__ temb,
                       const float* __restrict__ pemb,
                       const float* __restrict__ w,
                       float* __restrict__ xout) {
    int r = blockIdx.x;
    int s = r & (Sn - 1);
    int t = tok[r];
    const float* te = temb + (ll)t * Dn;
    const float* pe = pemb + (ll)s * Dn;
    float v[3]; float ss = 0.0f;
    #pragma unroll
    for (int u = 0; u < 3; u++) {
        int d = threadIdx.x + u * 256;
        v[u] = te[d] + pe[d];
        ss += v[u] * v[u];
    }
    float total = block_reduce_sum(ss);
    float inv = rsqrtf(total * (1.0f / Dn) + 1e-6f);
    #pragma unroll
    for (int u = 0; u < 3; u++) {
        int d = threadIdx.x + u * 256;
        xout[(ll)r * Dn + d] = v[u] * inv * w[d];
    }
}

// ---------------- rmsnorm ---------------------------------------------------
__global__ __launch_bounds__(256)
void rmsnorm_kernel(const float* __restrict__ in, const float* __restrict__ w,
                    float* __restrict__ out) {
    int r = blockIdx.x;
    const float* xr = in + (ll)r * Dn;
    float v[3]; float ss = 0.0f;
    #pragma unroll
    for (int u = 0; u < 3; u++) {
        int d = threadIdx.x + u * 256;
        v[u] = xr[d];
        ss += v[u] * v[u];
    }
    float total = block_reduce_sum(ss);
    float inv = rsqrtf(total * (1.0f / Dn) + 1e-6f);
    #pragma unroll
    for (int u = 0; u < 3; u++) {
        int d = threadIdx.x + u * 256;
        out[(ll)r * Dn + d] = v[u] * inv * w[d];
    }
}

// ---------------- causal softmax (in-place, row length S) -------------------
__global__ __launch_bounds__(256)
void softmax_kernel(float* __restrict__ sc) {
    float* p = sc + (ll)blockIdx.x * Sn;
    float v[4]; float mx = -3.0e38f;
    #pragma unroll
    for (int u = 0; u < 4; u++) {
        v[u] = p[threadIdx.x + u * 256];
        mx = fmaxf(mx, v[u]);
    }
    float m = block_reduce_max(mx);
    float sum = 0.0f;
    #pragma unroll
    for (int u = 0; u < 4; u++) {
        v[u] = __expf(v[u] - m);       // masked entries (-1e30) -> 0
        sum += v[u];
    }
    float s = block_reduce_sum(sum);
    float invs = 1.0f / s;
    #pragma unroll
    for (int u = 0; u < 4; u++) p[threadIdx.x + u * 256] = v[u] * invs;
}

// ---------------- SGEMM: 128x128x16 tiles, 8x8/thread ----------------------
// C[M,N] = epi( alpha * A @ op(B) ), batched over z = b*Hn + h via strides.
// EPI: 0 none, 1 +Res, 2 gelu.  TB: B given as [N,K] row-major (B^T used).
// MASK: causal (col > row -> -1e30), used for QK^T scores.
#define BM 128
#define BN 128
#define BK 16

template<int EPI, bool TB, bool MASK>
__global__ __launch_bounds__(256)
void gemm_kernel(const float* __restrict__ A, int lda, ll sAb, ll sAh,
                 const float* __restrict__ Bm, int ldb, ll sBb, ll sBh,
                 const float* __restrict__ Res, ll sRb, ll sRh,
                 float* __restrict__ C, int ldc, ll sCb, ll sCh,
                 int M, int N, int K, float alpha) {
    int zb = blockIdx.z / Hn;
    int zh = blockIdx.z % Hn;
    A  += zb * sAb + zh * sAh;
    Bm += zb * sBb + zh * sBh;
    C  += zb * sCb + zh * sCh;
    if (EPI == 1) Res += zb * sRb + zh * sRh;

    __shared__ float As[BK][BM];
    __shared__ float Bs[BK][BN];

    int tid = threadIdx.x;
    int tx = tid & 15, ty = tid >> 4;
    int row0 = blockIdx.y * BM;
    int col0 = blockIdx.x * BN;

    float acc[8][8] = {};

    for (int k0 = 0; k0 < K; k0 += BK) {
        // A tile [BM][BK] -> As[k][m] (transposed). 2 float4 per thread.
        #pragma unroll
        for (int t = 0; t < 2; t++) {
            int idx = tid + t * 256;          // 0..511
            int r   = idx >> 2;               // 0..127
            int k4  = (idx & 3) * 4;          // 0,4,8,12
            float4 va = make_float4(0.f, 0.f, 0.f, 0.f);
            if (row0 + r < M)
                va = *(const float4*)(A + (ll)(row0 + r) * lda + k0 + k4);
            As[k4 + 0][r] = va.x; As[k4 + 1][r] = va.y;
            As[k4 + 2][r] = va.z; As[k4 + 3][r] = va.w;
        }
        if (!TB) {
            // B tile [BK][BN], row-major [K,N]
            #pragma unroll
            for (int t = 0; t < 2; t++) {
                int idx = tid + t * 256;
                int k   = idx >> 5;           // 0..15
                int c4  = (idx & 31) * 4;     // 0..124
                int gc  = col0 + c4;
                float4 vb = make_float4(0.f, 0.f, 0.f, 0.f);
                const float* bp = Bm + (ll)(k0 + k) * ldb + gc;
                if (gc + 3 < N) {
                    vb = *(const float4*)bp;
                } else {
                    if (gc + 0 < N) vb.x = bp[0];
                    if (gc + 1 < N) vb.y = bp[1];
                    if (gc + 2 < N) vb.z = bp[2];
                }
                *(float4*)&Bs[k][c4] = vb;
            }
        } else {
            // B is [N][K] row-major; Bs[k][c] = B[col0+c][k0+k]
            #pragma unroll
            for (int t = 0; t < 2; t++) {
                int idx = tid + t * 256;
                int c   = idx >> 2;           // 0..127
                int k4  = (idx & 3) * 4;
                int gc  = col0 + c;
                float4 vb = make_float4(0.f, 0.f, 0.f, 0.f);
                if (gc < N)
                    vb = *(const float4*)(Bm + (ll)gc * ldb + k0 + k4);
                Bs[k4 + 0][c] = vb.x; Bs[k4 + 1][c] = vb.y;
                Bs[k4 + 2][c] = vb.z; Bs[k4 + 3][c] = vb.w;
            }
        }
        __syncthreads();

        #pragma unroll
        for (int kk = 0; kk < BK; kk++) {
            float4 a0 = *(const float4*)&As[kk][ty * 8];
            float4 a1 = *(const float4*)&As[kk][ty * 8 + 4];
            float4 b0 = *(const float4*)&Bs[kk][tx * 8];
            float4 b1 = *(const float4*)&Bs[kk][tx * 8 + 4];
            float ar[8] = {a0.x, a0.y, a0.z, a0.w, a1.x, a1.y, a1.z, a1.w};
            float br[8] = {b0.x, b0.y, b0.z, b0.w, b1.x, b1.y, b1.z, b1.w};
            #pragma unroll
            for (int i = 0; i < 8; i++)
                #pragma unroll
                for (int j = 0; j < 8; j++)
                    acc[i][j] = fmaf(ar[i], br[j], acc[i][j]);
        }
        __syncthreads();
    }

    #pragma unroll
    for (int i = 0; i < 8; i++) {
        int r = row0 + ty * 8 + i;
        if (r >= M) continue;
        #pragma unroll
        for (int j = 0; j < 8; j++) {
            int c = col0 + tx * 8 + j;
            if (c >= N) continue;
            float v = acc[i][j] * alpha;
            if (MASK && c > r) v = -1e30f;
            if (EPI == 1) v += Res[(ll)r * ldc + c];
            if (EPI == 2) v = gelu_tanh(v);
            C[(ll)r * ldc + c] = v;
        }
    }
}

// ---------------- host orchestration ---------------------------------------
extern "C" void kernel_launch(void* const* d_in, const int* in_sizes, int n_in,
                              void* d_out, int out_size) {
    const int*   tok  = (const int*)  d_in[0];
    const float* temb = (const float*)d_in[1];
    const float* pemb = (const float*)d_in[2];
    const float* pnw  = (const float*)d_in[3];
    const float* anw  = (const float*)d_in[4];
    const float* wq   = (const float*)d_in[5];
    const float* wk   = (const float*)d_in[6];
    const float* wv   = (const float*)d_in[7];
    const float* wo   = (const float*)d_in[8];
    const float* fnw  = (const float*)d_in[9];
    const float* w1   = (const float*)d_in[10];
    const float* w2   = (const float*)d_in[11];
    const float* onw  = (const float*)d_in[12];
    const float* oww  = (const float*)d_in[13];
    float* out = (float*)d_out;

    float *x, *xn, *q, *k, *v, *o, *sc, *ff;
    cudaGetSymbolAddress((void**)&x,  g_x);
    cudaGetSymbolAddress((void**)&xn, g_xn);
    cudaGetSymbolAddress((void**)&q,  g_q);
    cudaGetSymbolAddress((void**)&k,  g_k);
    cudaGetSymbolAddress((void**)&v,  g_v);
    cudaGetSymbolAddress((void**)&o,  g_o);
    cudaGetSymbolAddress((void**)&sc, g_sc);
    cudaGetSymbolAddress((void**)&ff, g_ff);

    const float scale = 1.0f / sqrtf((float)DHn);

    embed_norm_kernel<<<NTOK, 256>>>(tok, temb, pemb, pnw, x);

    dim3 gD(Dn / BN, NTOK / BM);              // (6,16)  2048 x 768
    dim3 gF(Fn / BN, NTOK / BM);              // (16,16) 2048 x 2048
    dim3 gSc(Sn / BN, Sn / BM, Bn * Hn);      // (8,8,16) scores per (b,h)
    dim3 gPV(1, Sn / BM, Bn * Hn);            // (1,8,16) probs @ V, N=96
    dim3 gV(Vn / BN, NTOK / BM);              // (250,16) logits

    const ll sQb = (ll)Sn * Dn, sQh = DHn;                    // q/k/v/o per-(b,h)
    const ll sScb = (ll)Hn * Sn * Sn, sSch = (ll)Sn * Sn;     // scores per-(b,h)

    for (int l = 0; l < Ln; l++) {
        rmsnorm_kernel<<<NTOK, 256>>>(x, anw + (ll)l * Dn, xn);

        gemm_kernel<0, false, false><<<gD, 256>>>(
            xn, Dn, 0, 0, wq + (ll)l * Dn * Dn, Dn, 0, 0,
            nullptr, 0, 0, q, Dn, 0, 0, NTOK, Dn, Dn, 1.0f);
        gemm_kernel<0, false, false><<<gD, 256>>>(
            xn, Dn, 0, 0, wk + (ll)l * Dn * Dn, Dn, 0, 0,
            nullptr, 0, 0, k, Dn, 0, 0, NTOK, Dn, Dn, 1.0f);
        gemm_kernel<0, false, false><<<gD, 256>>>(
            xn, Dn, 0, 0, wv + (ll)l * Dn * Dn, Dn, 0, 0,
            nullptr, 0, 0, v, Dn, 0, 0, NTOK, Dn, Dn, 1.0f);

        // scores = scale * Q @ K^T, causal mask
        gemm_kernel<0, true, true><<<gSc, 256>>>(
            q, Dn, sQb, sQh, k, Dn, sQb, sQh,
            nullptr, 0, 0, sc, Sn, sScb, sSch, Sn, Sn, DHn, scale);

        softmax_kernel<<<Bn * Hn * Sn, 256>>>(sc);

        // o = probs @ V
        gemm_kernel<0, false, false><<<gPV, 256>>>(
            sc, Sn, sScb, sSch, v, Dn, sQb, sQh,
            nullptr, 0, 0, o, Dn, sQb, sQh, Sn, DHn, Sn, 1.0f);

        // x = x + o @ Wo
        gemm_kernel<1, false, false><<<gD, 256>>>(
            o, Dn, 0, 0, wo + (ll)l * Dn * Dn, Dn, 0, 0,
            x, 0, 0, x, Dn, 0, 0, NTOK, Dn, Dn, 1.0f);

        rmsnorm_kernel<<<NTOK, 256>>>(x, fnw + (ll)l * Dn, xn);

        // ff = gelu(xn @ W1)
        gemm_kernel<2, false, false><<<gF, 256>>>(
            xn, Dn, 0, 0, w1 + (ll)l * Dn * Fn, Fn, 0, 0,
            nullptr, 0, 0, ff, Fn, 0, 0, NTOK, Fn, Dn, 1.0f);

        // x = x + ff @ W2
        gemm_kernel<1, false, false><<<gD, 256>>>(
            ff, Fn, 0, 0, w2 + (ll)l * Fn * Dn, Dn, 0, 0,
            x, 0, 0, x, Dn, 0, 0, NTOK, Dn, Fn, 1.0f);
    }

    rmsnorm_kernel<<<NTOK, 256>>>(x, onw, xn);

    // logits = xn @ out_w
    gemm_kernel<0, false, false><<<gV, 256>>>(
        xn, Dn, 0, 0, oww, Vn, 0, 0,
        nullptr, 0, 0, out, Vn, 0, 0, NTOK, Vn, Dn, 1.0f);
}